// round 9
// baseline (speedup 1.0000x reference)
#include <cuda_runtime.h>
#include <cuda_bf16.h>
#include <cstdint>

#define P     96
#define NN    9216
#define THR   0.9f
#define MAXM  1024                 // fast-path capacity (observed M ~ 922)
#define FULLM 0xffffffffu
#define GRID  148
#define BLK   256
#define NTHR  (GRID * BLK)

// device-global scratch (no runtime allocation allowed)
__device__ int      g_cnt;
__device__ __align__(128) int          g_bar_cnt;   // own L2 line
__device__ __align__(128) volatile int g_bar_flag;  // own L2 line
__device__ float    g_csc[NN];
__device__ int      g_cid[NN];
__device__ float4   g_cbx[NN];
__device__ float    g_sc[NN];
__device__ float4   g_bx[NN];
__device__ uint32_t g_mask32[MAXM * 32];            // row stride 32 = one 128B line

// grid-wide barrier (all GRID blocks co-resident; GRID <= SM count)
__device__ __forceinline__ void gbar(int phase)
{
    __syncthreads();
    if (threadIdx.x == 0) {
        __threadfence();
        if (atomicAdd(&g_bar_cnt, 1) == GRID - 1) {
            g_bar_cnt = 0;
            __threadfence();
            g_bar_flag = phase;
        } else {
            while (g_bar_flag < phase) { }
            __threadfence();
        }
    }
    __syncthreads();
}

__device__ __forceinline__ bool iou_gt(const float4 bi, const float ai, const float4 bj)
{
    const float ix1 = fmaxf(bi.x, bj.x);
    const float iy1 = fmaxf(bi.y, bj.y);
    const float ix2 = fminf(bi.z, bj.z);
    const float iy2 = fminf(bi.w, bj.w);
    const float iw = fmaxf(__fsub_rn(ix2, ix1), 0.0f);
    const float ih = fmaxf(__fsub_rn(iy2, iy1), 0.0f);
    const float inter = __fmul_rn(iw, ih);
    const float aj = __fmul_rn(__fsub_rn(bj.z, bj.x), __fsub_rn(bj.w, bj.y));
    const float uni = __fsub_rn(__fadd_rn(ai, aj), inter);
    return (uni > 0.0f) && (__fdiv_rn(inter, uni) > 0.5f);
}

__global__ void __launch_bounds__(BLK) k_all(
    const float* __restrict__ x, float* __restrict__ out, int out_size)
{
    __shared__ float    ss[MAXM];          // scores (rank phase)
    __shared__ int      sid[MAXM];         // ids    (rank phase)
    __shared__ float4   sbx[MAXM];         // boxes  (mask phase)
    __shared__ uint32_t sdiag[32 * 32];    // diagonal blocks (reduce)
    __shared__ uint32_t s_keepw[32];
    __shared__ uint32_t s_kb[NN / 32];     // slow-path kept bitmap

    const int tid  = threadIdx.x;
    const int gtid = blockIdx.x * BLK + tid;
    const int lane = tid & 31;
    const int widx = tid >> 5;             // warp within block (0..7)

    // ---------------- phase 0: zero output, compact valid boxes -------------
    for (int i = gtid; i < out_size; i += NTHR) out[i] = 0.0f;

    if (gtid < NN) {
        const float s = x[gtid];
        const bool valid = s > THR;
        const unsigned bal = __ballot_sync(FULLM, valid);
        if (valid) {
            const int leader = __ffs(bal) - 1;
            int base = 0;
            if (lane == leader) base = atomicAdd(&g_cnt, __popc(bal));
            base = __shfl_sync(bal, base, leader);
            const int pos = base + __popc(bal & ((1u << lane) - 1u));

            const float fi = (float)(gtid / P);
            const float fj = (float)(gtid % P);
            const float bx = __fadd_rn(__fmul_rn(x[1 * NN + gtid], 16.0f), __fmul_rn(fi, 16.0f));
            const float by = __fadd_rn(__fmul_rn(x[2 * NN + gtid], 16.0f), __fmul_rn(fj, 16.0f));
            const float bw = __fmul_rn(x[3 * NN + gtid], 1536.0f);
            const float bh = __fmul_rn(x[4 * NN + gtid], 1536.0f);

            g_csc[pos] = s;
            g_cid[pos] = gtid;
            g_cbx[pos] = make_float4(rintf(bx), rintf(by),
                                     rintf(__fadd_rn(bw, bx)), rintf(__fadd_rn(bh, by)));
        }
    }
    gbar(1);

    // ------- phase 1: warp-per-entry rank (stable) + immediate scatter ------
    const int M = g_cnt;
    if (M > 0 && M <= MAXM) {
        const int t0 = blockIdx.x * (BLK / 32);       // first entry of this block
        if (t0 < M) {
            for (int j = tid; j < M; j += BLK) { ss[j] = g_csc[j]; sid[j] = g_cid[j]; }
            __syncthreads();
            const int t = t0 + widx;
            if (t < M) {
                const float s  = ss[t];
                const int   id = sid[t];
                int r = 0;
                #pragma unroll 4
                for (int j = lane; j < M; j += 32) {
                    const float sj = ss[j];
                    const int   ij = sid[j];
                    r += (sj > s) || ((sj == s) && (ij < id));
                }
                r = __reduce_add_sync(FULLM, r);
                if (lane == 0) { g_sc[r] = s; g_bx[r] = g_cbx[t]; }
            }
        }
    } else if (M > MAXM) {
        // fallback: per-thread full scan (single writer -> scatter directly)
        for (int t = gtid; t < M; t += NTHR) {
            const float s  = g_csc[t];
            const int   id = g_cid[t];
            int r = 0;
            for (int j = 0; j < M; ++j) {
                const float sj = g_csc[j];
                const int   ij = g_cid[j];
                r += (sj > s) || ((sj == s) && (ij < id));
            }
            g_sc[r] = s;
            g_bx[r] = g_cbx[t];
        }
    }
    gbar(2);

    // ---------------- phase 2: suppression mask (smem boxes, ballot) --------
    if (M > 0 && M <= MAXM) {
        const int W  = (M + 31) >> 5;
        const int i0 = blockIdx.x * (BLK / 32);
        if (i0 < M) {
            for (int j = tid; j < M; j += BLK) sbx[j] = g_bx[j];
            __syncthreads();
            const int i = i0 + widx;
            if (i < M) {
                const float4 bi = sbx[i];
                const float  ai = __fmul_rn(__fsub_rn(bi.z, bi.x), __fsub_rn(bi.w, bi.y));
                uint32_t myword = 0u;
                for (int w = 0; w < W; ++w) {
                    const int j = (w << 5) + lane;
                    bool pred = false;
                    if (j < M) pred = iou_gt(bi, ai, sbx[j]);
                    const uint32_t word = __ballot_sync(FULLM, pred);
                    if (lane == w) myword = word;
                }
                g_mask32[i * 32 + lane] = (lane < W) ? myword : 0u;  // full 128B line
            }
        }
    }
    gbar(3);

    // ---------------- phase 3: greedy reduce (block 0 only) -----------------
    if (blockIdx.x != 0) return;
    const bool wk = (out_size >= 6 * NN);

    if (M > 0 && M <= MAXM) {
        const int W = (M + 31) >> 5;

        for (int idx = tid; idx < (W << 5); idx += BLK)
            sdiag[idx] = (idx < M) ? g_mask32[idx * 32 + (idx >> 5)] : 0u;
        __syncthreads();

        if (tid < 32) {
            const uint32_t above = ~((2u << lane) - 1u);   // bits strictly > lane
            uint32_t rem = 0u;
            uint32_t bufA[32], bufB[32];

            auto LOADA = [&](int base) {
                #pragma unroll
                for (int b = 0; b < 32; ++b) bufA[b] = g_mask32[(base + b) * 32 + lane];
            };
            auto LOADB = [&](int base) {
                #pragma unroll
                for (int b = 0; b < 32; ++b) bufB[b] = g_mask32[(base + b) * 32 + lane];
            };
            auto PROCESS = [&](uint32_t (&buf)[32], int w) {
                const int base = w << 5;
                const int nval = M - base;
                const uint32_t vmask = (nval >= 32) ? FULLM : ((1u << nval) - 1u);
                // diagonal row for this lane's box (bits strictly above lane)
                const uint32_t d = sdiag[base + lane] & above;
                const uint32_t rem_w = __shfl_sync(FULLM, rem, w);

                // EXACT serial greedy within the word: one iteration per
                // locally-kept box; suppressed boxes cost nothing.
                uint32_t kept = 0u;
                uint32_t t = (~rem_w) & vmask;
                while (t) {
                    const int b = __ffs(t) - 1;
                    kept |= (1u << b);
                    const uint32_t row_b = __shfl_sync(FULLM, d, b); // uniform b
                    t &= ~row_b;
                    t &= ~(1u << b);
                }
                if (lane == 0) s_keepw[w] = kept;

                // branch-free OR of kept rows into removed state
                uint32_t acc = 0u;
                #pragma unroll
                for (int b = 0; b < 32; ++b)
                    acc |= (kept & (1u << b)) ? buf[b] : 0u;
                rem |= acc;
            };

            LOADA(0);
            for (int w = 0; w < W; w += 2) {
                if (w + 1 < W) LOADB((w + 1) << 5);
                PROCESS(bufA, w);
                if (w + 2 < W) LOADA((w + 2) << 5);
                if (w + 1 < W) PROCESS(bufB, w + 1);
            }
        }
        __syncthreads();

        for (int i = tid; i < M; i += BLK) {
            if ((s_keepw[i >> 5] >> (i & 31)) & 1u) {
                const float4 bi = g_bx[i];
                out[i * 5 + 0] = g_sc[i];
                out[i * 5 + 1] = bi.x;
                out[i * 5 + 2] = bi.y;
                out[i * 5 + 3] = __fsub_rn(bi.z, bi.x);
                out[i * 5 + 4] = __fsub_rn(bi.w, bi.y);
                if (wk) out[5 * NN + i] = 1.0f;
            }
        }
    } else if (M > MAXM) {
        // correct-but-slow fallback (never expected: seed-fixed M ~ 922)
        for (int t = tid; t < NN / 32; t += BLK) s_kb[t] = 0u;
        __syncthreads();
        if (tid == 0) {
            for (int i = 0; i < M; ++i) {
                const float4 bi = g_bx[i];
                const float  ai = __fmul_rn(__fsub_rn(bi.z, bi.x), __fsub_rn(bi.w, bi.y));
                bool sup = false;
                for (int j = 0; j < i && !sup; ++j)
                    if ((s_kb[j >> 5] >> (j & 31)) & 1u)
                        sup = iou_gt(bi, ai, g_bx[j]);
                if (!sup) {
                    s_kb[i >> 5] |= 1u << (i & 31);
                    out[i * 5 + 0] = g_sc[i];
                    out[i * 5 + 1] = bi.x;
                    out[i * 5 + 2] = bi.y;
                    out[i * 5 + 3] = __fsub_rn(bi.z, bi.x);
                    out[i * 5 + 4] = __fsub_rn(bi.w, bi.y);
                    if (wk) out[5 * NN + i] = 1.0f;
                }
            }
        }
        __syncthreads();
    }

    // deterministic state for the next graph replay
    if (tid == 0) { g_cnt = 0; g_bar_flag = 0; }
}

// ---------------------------------------------------------------------------
extern "C" void kernel_launch(void* const* d_in, const int* in_sizes, int n_in,
                              void* d_out, int out_size)
{
    const float* x = (const float*)d_in[0];
    float* out = (float*)d_out;
    k_all<<<GRID, BLK>>>(x, out, out_size);
}

// round 10
// speedup vs baseline: 1.3418x; 1.3418x over previous
#include <cuda_runtime.h>
#include <cuda_bf16.h>
#include <cstdint>

#define P     96
#define NN    9216
#define THR   0.9f
#define MAXM  1024                 // fast-path capacity (observed M ~ 922)
#define FULLM 0xffffffffu
#define GRID  64
#define BLK   256
#define NTHR  (GRID * BLK)
#define DSMEM (MAXM * 32 * 4)      // 128KB dynamic smem: full mask for reduce

// device-global scratch (no runtime allocation allowed)
__device__ int      g_cnt;
__device__ __align__(128) int          g_bar_cnt;   // own L2 line
__device__ __align__(128) volatile int g_bar_flag;  // own L2 line
__device__ float    g_csc[NN];
__device__ int      g_cid[NN];
__device__ float4   g_cbx[NN];
__device__ float    g_sc[NN];
__device__ float4   g_bx[NN];
__device__ __align__(16) uint32_t g_mask32[MAXM * 32];  // row stride 32 = 128B line

// grid-wide barrier (all GRID blocks co-resident; GRID <= SM count)
__device__ __forceinline__ void gbar(int phase)
{
    __syncthreads();
    if (threadIdx.x == 0) {
        __threadfence();
        if (atomicAdd(&g_bar_cnt, 1) == GRID - 1) {
            g_bar_cnt = 0;
            __threadfence();
            g_bar_flag = phase;
        } else {
            while (g_bar_flag < phase) { }
            __threadfence();
        }
    }
    __syncthreads();
}

__device__ __forceinline__ bool iou_gt(const float4 bi, const float ai, const float4 bj)
{
    const float ix1 = fmaxf(bi.x, bj.x);
    const float iy1 = fmaxf(bi.y, bj.y);
    const float ix2 = fminf(bi.z, bj.z);
    const float iy2 = fminf(bi.w, bj.w);
    const float iw = fmaxf(__fsub_rn(ix2, ix1), 0.0f);
    const float ih = fmaxf(__fsub_rn(iy2, iy1), 0.0f);
    const float inter = __fmul_rn(iw, ih);
    const float aj = __fmul_rn(__fsub_rn(bj.z, bj.x), __fsub_rn(bj.w, bj.y));
    const float uni = __fsub_rn(__fadd_rn(ai, aj), inter);
    return (uni > 0.0f) && (__fdiv_rn(inter, uni) > 0.5f);
}

extern __shared__ uint32_t smask[];   // dynamic: staged mask (reduce phase)

__global__ void __launch_bounds__(BLK) k_all(
    const float* __restrict__ x, float* __restrict__ out, int out_size)
{
    __shared__ float    ss[MAXM];          // scores (rank phase)
    __shared__ int      sid[MAXM];         // ids    (rank phase)
    __shared__ float4   sbx[MAXM];         // boxes  (mask phase)
    __shared__ uint32_t sdiag[32 * 32];    // diagonal blocks (reduce)
    __shared__ uint32_t s_keepw[32];
    __shared__ uint32_t s_kb[NN / 32];     // slow-path kept bitmap

    const int tid  = threadIdx.x;
    const int gtid = blockIdx.x * BLK + tid;
    const int lane = tid & 31;
    const int widx = tid >> 5;             // warp within block (0..7)

    // ---------------- phase 0: zero output, compact valid boxes -------------
    for (int i = gtid; i < out_size; i += NTHR) out[i] = 0.0f;

    if (gtid < NN) {
        const float s = x[gtid];
        const bool valid = s > THR;
        const unsigned bal = __ballot_sync(FULLM, valid);
        if (valid) {
            const int leader = __ffs(bal) - 1;
            int base = 0;
            if (lane == leader) base = atomicAdd(&g_cnt, __popc(bal));
            base = __shfl_sync(bal, base, leader);
            const int pos = base + __popc(bal & ((1u << lane) - 1u));

            const float fi = (float)(gtid / P);
            const float fj = (float)(gtid % P);
            const float bx = __fadd_rn(__fmul_rn(x[1 * NN + gtid], 16.0f), __fmul_rn(fi, 16.0f));
            const float by = __fadd_rn(__fmul_rn(x[2 * NN + gtid], 16.0f), __fmul_rn(fj, 16.0f));
            const float bw = __fmul_rn(x[3 * NN + gtid], 1536.0f);
            const float bh = __fmul_rn(x[4 * NN + gtid], 1536.0f);

            g_csc[pos] = s;
            g_cid[pos] = gtid;
            g_cbx[pos] = make_float4(rintf(bx), rintf(by),
                                     rintf(__fadd_rn(bw, bx)), rintf(__fadd_rn(bh, by)));
        }
    }
    gbar(1);

    // ------- phase 1: warp-per-entry rank (stable) + immediate scatter ------
    const int M = g_cnt;
    if (M > 0 && M <= MAXM) {
        for (int j = tid; j < M; j += BLK) { ss[j] = g_csc[j]; sid[j] = g_cid[j]; }
        __syncthreads();
        for (int t = blockIdx.x * (BLK / 32) + widx; t < M; t += GRID * (BLK / 32)) {
            const float s  = ss[t];
            const int   id = sid[t];
            int r = 0;
            #pragma unroll 4
            for (int j = lane; j < M; j += 32) {
                const float sj = ss[j];
                const int   ij = sid[j];
                r += (sj > s) || ((sj == s) && (ij < id));
            }
            r = __reduce_add_sync(FULLM, r);
            if (lane == 0) { g_sc[r] = s; g_bx[r] = g_cbx[t]; }
        }
    } else if (M > MAXM) {
        for (int t = gtid; t < M; t += NTHR) {
            const float s  = g_csc[t];
            const int   id = g_cid[t];
            int r = 0;
            for (int j = 0; j < M; ++j) {
                const float sj = g_csc[j];
                const int   ij = g_cid[j];
                r += (sj > s) || ((sj == s) && (ij < id));
            }
            g_sc[r] = s;
            g_bx[r] = g_cbx[t];
        }
    }
    gbar(2);

    // ---------------- phase 2: suppression mask (smem boxes, ballot) --------
    if (M > 0 && M <= MAXM) {
        const int W = (M + 31) >> 5;
        for (int j = tid; j < M; j += BLK) sbx[j] = g_bx[j];
        __syncthreads();
        for (int i = blockIdx.x * (BLK / 32) + widx; i < M; i += GRID * (BLK / 32)) {
            const float4 bi = sbx[i];
            const float  ai = __fmul_rn(__fsub_rn(bi.z, bi.x), __fsub_rn(bi.w, bi.y));
            uint32_t myword = 0u;
            for (int w = 0; w < W; ++w) {
                const int j = (w << 5) + lane;
                bool pred = false;
                if (j < M) pred = iou_gt(bi, ai, sbx[j]);
                const uint32_t word = __ballot_sync(FULLM, pred);
                if (lane == w) myword = word;
            }
            g_mask32[i * 32 + lane] = (lane < W) ? myword : 0u;  // full 128B line
        }
    }
    gbar(3);

    // ---------------- phase 3: greedy reduce (block 0 only) -----------------
    if (blockIdx.x != 0) return;
    const bool wk = (out_size >= 6 * NN);

    if (M > 0 && M <= MAXM) {
        const int W = (M + 31) >> 5;
        const int words = M * 32;

        // all 8 warps stage the full mask into dynamic smem (uint4 vectorized)
        {
            const uint4* __restrict__ src4 = reinterpret_cast<const uint4*>(g_mask32);
            uint4* dst4 = reinterpret_cast<uint4*>(smask);
            for (int t = tid; t < (words >> 2); t += BLK) dst4[t] = src4[t];
        }
        // diagonal blocks (transposed, conflict-free for the walk)
        for (int idx = tid; idx < (W << 5); idx += BLK)
            sdiag[idx] = (idx < M) ? g_mask32[idx * 32 + (idx >> 5)] : 0u;
        __syncthreads();

        if (tid < 32) {
            const uint32_t mybit = 1u << lane;
            const uint32_t above = ~((2u << lane) - 1u);   // bits strictly > lane
            uint32_t rem = 0u;

            for (int w = 0; w < W; ++w) {
                const int base = w << 5;

                // row data for this word: conflict-free LDS, fully pipelined
                uint32_t buf[32];
                #pragma unroll
                for (int b = 0; b < 32; ++b)
                    buf[b] = smask[(base + b) * 32 + lane];

                const int nval = M - base;
                const uint32_t vmask = (nval >= 32) ? FULLM : ((1u << nval) - 1u);
                const uint32_t rem_w = __shfl_sync(FULLM, rem, w);
                const uint32_t cand  = (~rem_w) & vmask;
                const uint32_t d = sdiag[base + lane] & above;

                // Jacobi fixpoint (unroll 2 per convergence check).
                // Prefix-stabilization: bits 0..t-1 exact after t iters; the
                // only stationary point is the unique greedy fixpoint.
                uint32_t kept = cand;
                for (;;) {
                    uint32_t sup = __reduce_or_sync(FULLM, (kept & mybit) ? d : 0u);
                    const uint32_t k1 = cand & ~sup;
                    sup = __reduce_or_sync(FULLM, (k1 & mybit) ? d : 0u);
                    const uint32_t k2 = cand & ~sup;
                    if (k2 == k1) { kept = k2; break; }
                    if (k2 == kept) break;      // safety (cannot 2-cycle, see above)
                    kept = k2;
                }
                if (lane == 0) s_keepw[w] = kept;

                // branch-free OR of kept rows into removed state
                uint32_t acc = 0u;
                #pragma unroll
                for (int b = 0; b < 32; ++b)
                    acc |= (kept & (1u << b)) ? buf[b] : 0u;
                rem |= acc;
            }
        }
        __syncthreads();

        for (int i = tid; i < M; i += BLK) {
            if ((s_keepw[i >> 5] >> (i & 31)) & 1u) {
                const float4 bi = g_bx[i];
                out[i * 5 + 0] = g_sc[i];
                out[i * 5 + 1] = bi.x;
                out[i * 5 + 2] = bi.y;
                out[i * 5 + 3] = __fsub_rn(bi.z, bi.x);
                out[i * 5 + 4] = __fsub_rn(bi.w, bi.y);
                if (wk) out[5 * NN + i] = 1.0f;
            }
        }
    } else if (M > MAXM) {
        // correct-but-slow fallback (never expected: seed-fixed M ~ 922)
        for (int t = tid; t < NN / 32; t += BLK) s_kb[t] = 0u;
        __syncthreads();
        if (tid == 0) {
            for (int i = 0; i < M; ++i) {
                const float4 bi = g_bx[i];
                const float  ai = __fmul_rn(__fsub_rn(bi.z, bi.x), __fsub_rn(bi.w, bi.y));
                bool sup = false;
                for (int j = 0; j < i && !sup; ++j)
                    if ((s_kb[j >> 5] >> (j & 31)) & 1u)
                        sup = iou_gt(bi, ai, g_bx[j]);
                if (!sup) {
                    s_kb[i >> 5] |= 1u << (i & 31);
                    out[i * 5 + 0] = g_sc[i];
                    out[i * 5 + 1] = bi.x;
                    out[i * 5 + 2] = bi.y;
                    out[i * 5 + 3] = __fsub_rn(bi.z, bi.x);
                    out[i * 5 + 4] = __fsub_rn(bi.w, bi.y);
                    if (wk) out[5 * NN + i] = 1.0f;
                }
            }
        }
        __syncthreads();
    }

    // deterministic state for the next graph replay
    if (tid == 0) { g_cnt = 0; g_bar_flag = 0; }
}

// ---------------------------------------------------------------------------
extern "C" void kernel_launch(void* const* d_in, const int* in_sizes, int n_in,
                              void* d_out, int out_size)
{
    const float* x = (const float*)d_in[0];
    float* out = (float*)d_out;
    cudaFuncSetAttribute(k_all, cudaFuncAttributeMaxDynamicSharedMemorySize, DSMEM);
    k_all<<<GRID, BLK, DSMEM>>>(x, out, out_size);
}